// round 9
// baseline (speedup 1.0000x reference)
#include <cuda_runtime.h>
#include <cuda_bf16.h>

// LIF spike scan: x [B=32, T=16, C=128, H=32, W=32] fp32 -> spikes (fp32, same shape).
// Per site: mem = mem*TAU + x_t; s = (mem >= THRESH); mem = (1-s)*mem.
//
// HBM-bound, 512 MiB irreducible 1:1 R/W traffic; all healthy variants
// saturate ~6.4 TB/s (practical mixed R/W HBM3e wall). R9 = last micro-cell:
// R4's group-of-4 streaming structure (compiles to 32 regs -> ~87% occupancy,
// 6412 GB/s) + R5's index micro-opts (compile-time shapes -> shift/mask,
// 32-bit addressing, exact grid / no guard) to cut the alu-pipe prologue
// (18% -> ~10%) so warps enqueue loads earlier.
// Known traps: never cap regs under full 16-deep ldcs batching (R7: spills,
// -25%); block=512 hurts (R6).

#define LIF_T      16
#define LIF_THRESH 0.5f
#define LIF_TAU    0.25f
#define LIF_CHW4   32768           // C*H*W/4 = 128*32*32/4 (compile-time)
#define LIF_G      4               // timesteps per load/compute/store group

__global__ __launch_bounds__(256) void lif_spike_kernel(
    const float4* __restrict__ x,   // [B, T, CHW/4] viewed as float4
    float4* __restrict__ out)
{
    // gid in [0, B*CHW4) = [0, 1048576); all indices fit 32-bit.
    unsigned gid = blockIdx.x * blockDim.x + threadIdx.x;
    unsigned b   = gid >> 15;              // gid / LIF_CHW4
    unsigned sp  = gid & (LIF_CHW4 - 1);   // gid % LIF_CHW4

    // float4 offset of (b, t=0, sp); max = 32*16*32768 = 2^24, fits 32-bit.
    unsigned base = b * (LIF_T * LIF_CHW4) + sp;

    float4 mem = make_float4(0.f, 0.f, 0.f, 0.f);

#pragma unroll
    for (int g = 0; g < LIF_T / LIF_G; g++) {
        float4 v[LIF_G];

        // batch this group's streaming loads (4 outstanding LDG.128 per thread)
#pragma unroll
        for (int t = 0; t < LIF_G; t++) {
            v[t] = __ldcs(&x[base + (g * LIF_G + t) * LIF_CHW4]);
        }

        // sequential LIF scan, 4 lanes in parallel
#pragma unroll
        for (int t = 0; t < LIF_G; t++) {
            mem.x = fmaf(mem.x, LIF_TAU, v[t].x);
            mem.y = fmaf(mem.y, LIF_TAU, v[t].y);
            mem.z = fmaf(mem.z, LIF_TAU, v[t].z);
            mem.w = fmaf(mem.w, LIF_TAU, v[t].w);

            float sx = (mem.x >= LIF_THRESH) ? 1.f : 0.f;
            float sy = (mem.y >= LIF_THRESH) ? 1.f : 0.f;
            float sz = (mem.z >= LIF_THRESH) ? 1.f : 0.f;
            float sw = (mem.w >= LIF_THRESH) ? 1.f : 0.f;

            // hard reset
            mem.x = (sx != 0.f) ? 0.f : mem.x;
            mem.y = (sy != 0.f) ? 0.f : mem.y;
            mem.z = (sz != 0.f) ? 0.f : mem.z;
            mem.w = (sw != 0.f) ? 0.f : mem.w;

            v[t] = make_float4(sx, sy, sz, sw);
        }

        // batch this group's streaming stores (evict-first)
#pragma unroll
        for (int t = 0; t < LIF_G; t++) {
            __stcs(&out[base + (g * LIF_G + t) * LIF_CHW4], v[t]);
        }
    }
}

extern "C" void kernel_launch(void* const* d_in, const int* in_sizes, int n_in,
                              void* d_out, int out_size)
{
    const float* x = (const float*)d_in[0];
    float* out = (float*)d_out;

    // x: [32, 16, 128, 32, 32]; n_sites = 32 * 32768 = 1,048,576 float4 sites.
    const int chw  = 128 * 32 * 32;
    const int B    = in_sizes[0] / (LIF_T * chw);   // 32
    const int n_sites = B * LIF_CHW4;               // 1,048,576

    const int threads = 256;
    const int blocks = n_sites / threads;           // 4096, exact

    lif_spike_kernel<<<blocks, threads>>>((const float4*)x, (float4*)out);
}

// round 10
// speedup vs baseline: 1.0211x; 1.0211x over previous
#include <cuda_runtime.h>
#include <cuda_bf16.h>

// LIF spike scan: x [B=32, T=16, C=128, H=32, W=32] fp32 -> spikes (fp32, same shape).
// Per site: mem = mem*TAU + x_t; s = (mem >= THRESH); mem = (1-s)*mem.
//
// FINAL (R5 — best of 9 probed variants, 82.0us / ~6.4 TB/s):
// HBM-bound, 512 MiB irreducible 1:1 R/W traffic. Nine variants spanning
// occupancy 21-87%, per-warp MLP 2-16, cache hints, block 256/512, and reg
// caps all plateau at 6.29-6.43 TB/s => practical mixed R/W HBM3e wall
// (~80% of 8 TB/s spec), per-variant deltas below bench noise.
// Structure:
//  - one float4 per thread, perfectly coalesced (512B/warp/access)
//  - all 16 time-step loads batched as streaming (__ldcs, evict-first; zero reuse)
//  - sequential LIF scan entirely in registers
//  - 16 streaming stores (__stcs)
//  - compile-time shapes (div -> shift/mask), 32-bit indexing, exact grid
// Traps confirmed this session: reg caps spill the 16-deep batch (R7, -25%);
// block=512 costs concurrency (R6).

#define LIF_T      16
#define LIF_THRESH 0.5f
#define LIF_TAU    0.25f
#define LIF_CHW4   32768           // C*H*W/4 = 128*32*32/4 (compile-time)

__global__ __launch_bounds__(256) void lif_spike_kernel(
    const float4* __restrict__ x,   // [B, T, CHW/4] viewed as float4
    float4* __restrict__ out)
{
    // gid in [0, B*CHW4) = [0, 1048576); all indices fit 32-bit.
    unsigned gid = blockIdx.x * blockDim.x + threadIdx.x;
    unsigned b   = gid >> 15;              // gid / LIF_CHW4
    unsigned sp  = gid & (LIF_CHW4 - 1);   // gid % LIF_CHW4

    // float4 offset of (b, t=0, sp); max = 32*16*32768 = 2^24, fits 32-bit.
    unsigned base = b * (LIF_T * LIF_CHW4) + sp;

    // All 16 time-step loads are independent; streaming (evict-first).
    float4 v[LIF_T];
#pragma unroll
    for (int t = 0; t < LIF_T; t++) {
        v[t] = __ldcs(&x[base + t * LIF_CHW4]);
    }

    // Sequential LIF scan in registers, 4 lanes in parallel.
    float4 mem = make_float4(0.f, 0.f, 0.f, 0.f);
#pragma unroll
    for (int t = 0; t < LIF_T; t++) {
        mem.x = fmaf(mem.x, LIF_TAU, v[t].x);
        mem.y = fmaf(mem.y, LIF_TAU, v[t].y);
        mem.z = fmaf(mem.z, LIF_TAU, v[t].z);
        mem.w = fmaf(mem.w, LIF_TAU, v[t].w);

        float sx = (mem.x >= LIF_THRESH) ? 1.f : 0.f;
        float sy = (mem.y >= LIF_THRESH) ? 1.f : 0.f;
        float sz = (mem.z >= LIF_THRESH) ? 1.f : 0.f;
        float sw = (mem.w >= LIF_THRESH) ? 1.f : 0.f;

        // hard reset
        mem.x = (sx != 0.f) ? 0.f : mem.x;
        mem.y = (sy != 0.f) ? 0.f : mem.y;
        mem.z = (sz != 0.f) ? 0.f : mem.z;
        mem.w = (sw != 0.f) ? 0.f : mem.w;

        v[t] = make_float4(sx, sy, sz, sw);   // reuse v[] as output buffer
    }

#pragma unroll
    for (int t = 0; t < LIF_T; t++) {
        __stcs(&out[base + t * LIF_CHW4], v[t]);
    }
}

extern "C" void kernel_launch(void* const* d_in, const int* in_sizes, int n_in,
                              void* d_out, int out_size)
{
    const float* x = (const float*)d_in[0];
    float* out = (float*)d_out;

    // x: [32, 16, 128, 32, 32]; n_sites = 32 * 32768 = 1,048,576 float4 sites.
    const int chw  = 128 * 32 * 32;
    const int B    = in_sizes[0] / (LIF_T * chw);   // 32
    const int n_sites = B * LIF_CHW4;               // 1,048,576

    const int threads = 256;
    const int blocks = n_sites / threads;           // 4096, exact

    lif_spike_kernel<<<blocks, threads>>>((const float4*)x, (float4*)out);
}

// round 11
// speedup vs baseline: 1.0219x; 1.0008x over previous
#include <cuda_runtime.h>
#include <cuda_bf16.h>

// LIF spike scan: x [B=32, T=16, C=128, H=32, W=32] fp32 -> spikes (fp32, same shape).
// Per site: mem = mem*TAU + x_t; s = (mem >= THRESH); mem = (1-s)*mem.
//
// HBM-bound, 512 MiB irreducible 1:1 R/W traffic; healthy variants plateau at
// 6.3-6.4 TB/s (mixed R/W HBM3e wall). R11: two-stage software pipeline —
// load t=0..7, issue loads t=8..15, then compute+store half 1 (overlapping
// DRAM-side with half-2 reads), then compute+store half 2. Changes read/write
// phasing from monolithic 16R->16W bursts to interleaved mixed streams
// (friendlier to DRAM bus-turnaround scheduling). Peak 16 float4 live => same
// ~80 regs as R5, no reg cap (R7 spill trap), block=256 (R6 trap).

#define LIF_T      16
#define LIF_H      8               // half
#define LIF_THRESH 0.5f
#define LIF_TAU    0.25f
#define LIF_CHW4   32768           // C*H*W/4 = 128*32*32/4 (compile-time)

__device__ __forceinline__ float4 lif_step(float4& mem, float4 xin)
{
    mem.x = fmaf(mem.x, LIF_TAU, xin.x);
    mem.y = fmaf(mem.y, LIF_TAU, xin.y);
    mem.z = fmaf(mem.z, LIF_TAU, xin.z);
    mem.w = fmaf(mem.w, LIF_TAU, xin.w);

    float sx = (mem.x >= LIF_THRESH) ? 1.f : 0.f;
    float sy = (mem.y >= LIF_THRESH) ? 1.f : 0.f;
    float sz = (mem.z >= LIF_THRESH) ? 1.f : 0.f;
    float sw = (mem.w >= LIF_THRESH) ? 1.f : 0.f;

    mem.x = (sx != 0.f) ? 0.f : mem.x;
    mem.y = (sy != 0.f) ? 0.f : mem.y;
    mem.z = (sz != 0.f) ? 0.f : mem.z;
    mem.w = (sw != 0.f) ? 0.f : mem.w;

    return make_float4(sx, sy, sz, sw);
}

__global__ __launch_bounds__(256) void lif_spike_kernel(
    const float4* __restrict__ x,   // [B, T, CHW/4] viewed as float4
    float4* __restrict__ out)
{
    // gid in [0, B*CHW4) = [0, 1048576); all indices fit 32-bit.
    unsigned gid = blockIdx.x * blockDim.x + threadIdx.x;
    unsigned b   = gid >> 15;              // gid / LIF_CHW4
    unsigned sp  = gid & (LIF_CHW4 - 1);   // gid % LIF_CHW4

    unsigned base = b * (LIF_T * LIF_CHW4) + sp;   // max 2^24, fits 32-bit

    // Stage 0: loads for first half (streaming, evict-first)
    float4 va[LIF_H];
#pragma unroll
    for (int t = 0; t < LIF_H; t++) {
        va[t] = __ldcs(&x[base + t * LIF_CHW4]);
    }

    // Stage 1: issue second-half loads BEFORE first-half compute,
    // so they are in flight while half 1 computes/stores.
    float4 vb[LIF_H];
#pragma unroll
    for (int t = 0; t < LIF_H; t++) {
        vb[t] = __ldcs(&x[base + (LIF_H + t) * LIF_CHW4]);
    }

    // Compute + store half 1 (stores overlap with half-2 reads DRAM-side)
    float4 mem = make_float4(0.f, 0.f, 0.f, 0.f);
#pragma unroll
    for (int t = 0; t < LIF_H; t++) {
        float4 s = lif_step(mem, va[t]);
        __stcs(&out[base + t * LIF_CHW4], s);
    }

    // Compute + store half 2
#pragma unroll
    for (int t = 0; t < LIF_H; t++) {
        float4 s = lif_step(mem, vb[t]);
        __stcs(&out[base + (LIF_H + t) * LIF_CHW4], s);
    }
}

extern "C" void kernel_launch(void* const* d_in, const int* in_sizes, int n_in,
                              void* d_out, int out_size)
{
    const float* x = (const float*)d_in[0];
    float* out = (float*)d_out;

    // x: [32, 16, 128, 32, 32]; n_sites = 32 * 32768 = 1,048,576 float4 sites.
    const int chw  = 128 * 32 * 32;
    const int B    = in_sizes[0] / (LIF_T * chw);   // 32
    const int n_sites = B * LIF_CHW4;               // 1,048,576

    const int threads = 256;
    const int blocks = n_sites / threads;           // 4096, exact

    lif_spike_kernel<<<blocks, threads>>>((const float4*)x, (float4*)out);
}